// round 10
// baseline (speedup 1.0000x reference)
#include <cuda_runtime.h>

#define Hn 9
#define Wn 10
#define Dn 5
#define KD 3            // Dn/2 + 1
#define DIMC 1000
#define NSP (Hn*Wn*Dn)  // 450
#define CT 20           // channels per block tile (1000/20 = 50 tiles)
#define NTHREADS 256
#define SC (1.0f/450.0f)

// ---- compile-time twiddle literals (FFMA immediates) ----
#define C51  0.30901699437494745f
#define C52 (-0.8090169943749475f)
#define S51  0.9510565162951535f
#define S52  0.5877852522924731f
#define S3   0.8660254037844386f
#define C91  0.766044443118978f
#define S91  0.6427876096865393f
#define C92  0.17364817766693041f
#define S92  0.984807753012208f
#define C94 (-0.9396926207859084f)
#define S94  0.3420201433256687f
#define C101 0.8090169943749475f
#define S101 0.5877852522924731f
#define C102 0.30901699437494745f
#define S102 0.9510565162951535f
// output-stage constants with 1/450 and the rfft doubling folded in
#define TWOSC (2.0f*SC)
#define C51T (2.0f*SC*C51)
#define C52T (2.0f*SC*C52)
#define S51T (2.0f*SC*S51)
#define S52T (2.0f*SC*S52)

__device__ __forceinline__ float2 cadd(float2 a, float2 b){ return make_float2(a.x+b.x, a.y+b.y); }
__device__ __forceinline__ float2 csub(float2 a, float2 b){ return make_float2(a.x-b.x, a.y-b.y); }
__device__ __forceinline__ float2 cmul(float2 a, float c, float s){
    return make_float2(a.x*c - a.y*s, a.y*c + a.x*s);
}
__device__ __forceinline__ float2 wmul(float2 a, float2 g){
    return make_float2(a.x*g.x - a.y*g.y, a.x*g.y + a.y*g.x);
}

template<int SGN>
__device__ __forceinline__ void dft3(float2 a0, float2 a1, float2 a2,
                                     float2& X0, float2& X1, float2& X2){
    float2 t = cadd(a1,a2), d = csub(a1,a2);
    X0 = cadd(a0,t);
    float mr = fmaf(-0.5f, t.x, a0.x);
    float mi = fmaf(-0.5f, t.y, a0.y);
    const float s = (SGN > 0) ? S3 : -S3;
    X1 = make_float2(fmaf( s, d.y, mr), fmaf(-s, d.x, mi));
    X2 = make_float2(fmaf(-s, d.y, mr), fmaf( s, d.x, mi));
}

template<int SGN>
__device__ __forceinline__ void dft5(float2 a0, float2 a1, float2 a2, float2 a3, float2 a4,
                                     float2& X0, float2& X1, float2& X2, float2& X3, float2& X4){
    float2 t1 = cadd(a1,a4), t2 = cadd(a2,a3), t3 = csub(a1,a4), t4 = csub(a2,a3);
    X0 = make_float2(a0.x + t1.x + t2.x, a0.y + t1.y + t2.y);
    float u1r = a0.x + C51*t1.x + C52*t2.x;
    float u1i = a0.y + C51*t1.y + C52*t2.y;
    float v1r = S51*t3.x + S52*t4.x;
    float v1i = S51*t3.y + S52*t4.y;
    float u2r = a0.x + C52*t1.x + C51*t2.x;
    float u2i = a0.y + C52*t1.y + C51*t2.y;
    float v2r = S52*t3.x - S51*t4.x;
    float v2i = S52*t3.y - S51*t4.y;
    if (SGN > 0){
        X1 = make_float2(u1r + v1i, u1i - v1r);
        X4 = make_float2(u1r - v1i, u1i + v1r);
        X2 = make_float2(u2r + v2i, u2i - v2r);
        X3 = make_float2(u2r - v2i, u2i + v2r);
    } else {
        X1 = make_float2(u1r - v1i, u1i + v1r);
        X4 = make_float2(u1r + v1i, u1i - v1r);
        X2 = make_float2(u2r - v2i, u2i + v2r);
        X3 = make_float2(u2r + v2i, u2i - v2r);
    }
}

// 10-pt FFT on ten named scalars, radix 2x5 DIT
template<int SGN>
__device__ __forceinline__ void fft10s(float2&x0, float2&x1, float2&x2, float2&x3, float2&x4,
                                       float2&x5, float2&x6, float2&x7, float2&x8, float2&x9){
    float2 E0,E1,E2,E3,E4, O0,O1,O2,O3,O4;
    dft5<SGN>(x0,x2,x4,x6,x8, E0,E1,E2,E3,E4);
    dft5<SGN>(x1,x3,x5,x7,x9, O0,O1,O2,O3,O4);
    const float sg = (SGN > 0) ? -1.0f : 1.0f;
    float2 T1 = cmul(O1,  C101, sg*S101);
    float2 T2 = cmul(O2,  C102, sg*S102);
    float2 T3 = cmul(O3, -C102, sg*S102);
    float2 T4 = cmul(O4, -C101, sg*S101);
    x0=cadd(E0,O0); x5=csub(E0,O0);
    x1=cadd(E1,T1); x6=csub(E1,T1);
    x2=cadd(E2,T2); x7=csub(E2,T2);
    x3=cadd(E3,T3); x8=csub(E3,T3);
    x4=cadd(E4,T4); x9=csub(E4,T4);
}

// rfft5 for one channel component (CMP of the float4s v0..v4)
#define RFFT5C(CMP, QR0,QI0, QR1,QI1, QR2,QI2) do{ \
    float t1=v1.CMP+v4.CMP, t2=v2.CMP+v3.CMP, t3=v1.CMP-v4.CMP, t4=v2.CMP-v3.CMP; \
    QR0 = v0.CMP + t1 + t2;                 QI0 = 0.0f; \
    QR1 = v0.CMP + C51*t1 + C52*t2;         QI1 = -(S51*t3 + S52*t4); \
    QR2 = v0.CMP + C52*t1 + C51*t2;         QI2 = -(S52*t3 - S51*t4); \
}while(0)

// irfft5 for one channel: inputs (re0, r1,i1, r2,i2), outputs O0..O4
#define IRFFT5C(RE0, R1, I1, R2, I2, O0,O1,O2,O3,O4) do{ \
    float s0 = SC*(RE0); \
    float pA = s0 + C51T*(R1) + C52T*(R2); \
    float qA = S51T*(I1) + S52T*(I2); \
    float pB = s0 + C52T*(R1) + C51T*(R2); \
    float qB = S52T*(I1) - S51T*(I2); \
    O0 = s0 + TWOSC*((R1)+(R2)); \
    O1 = pA - qA; O2 = pB - qB; O3 = pB + qB; O4 = pA + qA; \
}while(0)

#define STOREP() do { \
    z[zb + 0*(KD*CT)] = p0; z[zb + 1*(KD*CT)] = p1; \
    z[zb + 2*(KD*CT)] = p2; z[zb + 3*(KD*CT)] = p3; \
    z[zb + 4*(KD*CT)] = p4; z[zb + 5*(KD*CT)] = p5; \
    z[zb + 6*(KD*CT)] = p6; z[zb + 7*(KD*CT)] = p7; \
    z[zb + 8*(KD*CT)] = p8; z[zb + 9*(KD*CT)] = p9; \
} while(0)

#define LOADP() do { \
    p0 = z[zb + 0*(KD*CT)]; p1 = z[zb + 1*(KD*CT)]; \
    p2 = z[zb + 2*(KD*CT)]; p3 = z[zb + 3*(KD*CT)]; \
    p4 = z[zb + 4*(KD*CT)]; p5 = z[zb + 5*(KD*CT)]; \
    p6 = z[zb + 6*(KD*CT)]; p7 = z[zb + 7*(KD*CT)]; \
    p8 = z[zb + 8*(KD*CT)]; p9 = z[zb + 9*(KD*CT)]; \
} while(0)

// Shared layout: z[((h*Wn + w)*KD + k)*CT + c] as float2 (43.2 KB static)
__global__ void __launch_bounds__(NTHREADS, 5)
gf_kernel(const float* __restrict__ x, const float2* __restrict__ cw2,
          float* __restrict__ out)
{
    __shared__ float2 z[Hn*Wn*KD*CT];

    const int b   = blockIdx.x;
    const int c0  = blockIdx.y * CT;
    const int tid = threadIdx.x;
    const long xbase = (long)b * NSP * DIMC + c0;

    // ---- Phase 1: rfft5 along d, 4 channels per thread (float4 I/O)
    for (int it = tid; it < Hn*Wn*(CT/4); it += NTHREADS) {
        int c4 = it % (CT/4);
        int hw = it / (CT/4);
        const float* px = x + xbase + (long)hw * (Dn*DIMC) + c4*4;
        float4 v0 = *(const float4*)(px);
        float4 v1 = *(const float4*)(px + DIMC);
        float4 v2 = *(const float4*)(px + 2*DIMC);
        float4 v3 = *(const float4*)(px + 3*DIMC);
        float4 v4 = *(const float4*)(px + 4*DIMC);
        float4 q0a,q0b,q1a,q1b,q2a,q2b;   // kX, channels (0,1) then (2,3)
        RFFT5C(x, q0a.x,q0a.y, q1a.x,q1a.y, q2a.x,q2a.y);
        RFFT5C(y, q0a.z,q0a.w, q1a.z,q1a.w, q2a.z,q2a.w);
        RFFT5C(z, q0b.x,q0b.y, q1b.x,q1b.y, q2b.x,q2b.y);
        RFFT5C(w, q0b.z,q0b.w, q1b.z,q1b.w, q2b.z,q2b.w);
        int sb = (hw*KD)*CT + c4*4;       // float2 index, even -> 16B aligned
        *(float4*)&z[sb]          = q0a;  *(float4*)&z[sb + 2]        = q0b;
        *(float4*)&z[sb + CT]     = q1a;  *(float4*)&z[sb + CT + 2]   = q1b;
        *(float4*)&z[sb + 2*CT]   = q2a;  *(float4*)&z[sb + 2*CT + 2] = q2b;
    }
    __syncthreads();

    // ---- Phase 2: forward FFT along w (radix 2x5), registers
    for (int it = tid; it < Hn*KD*CT; it += NTHREADS) {
        int c  = it % CT;
        int hk = it / CT;
        int h = hk / KD, k = hk % KD;
        int zb = (h*Wn*KD + k)*CT + c;
        float2 p0,p1,p2,p3,p4,p5,p6,p7,p8,p9;
        LOADP();
        fft10s<+1>(p0,p1,p2,p3,p4,p5,p6,p7,p8,p9);
        STOREP();
    }
    __syncthreads();

    // ---- Phase 3: fwd 9-pt (3x3) -> weight -> inv 9-pt, interleaved groups
    {
        const int HS = Wn*KD*CT;
        const int WS = Wn*KD*DIMC;
        for (int it = tid; it < Wn*KD*CT; it += NTHREADS) {
            int c  = it % CT;
            int wk = it / CT;
            int w = wk / KD, k = wk % KD;
            int base = (w*KD + k)*CT + c;
            const float2* cwp = cw2 + (long)((w*KD) + k)*DIMC + c0 + c;

            float2 a0=z[base+0*HS], a1=z[base+1*HS], a2=z[base+2*HS],
                   a3=z[base+3*HS], a4=z[base+4*HS], a5=z[base+5*HS],
                   a6=z[base+6*HS], a7=z[base+7*HS], a8=z[base+8*HS];
            // forward stage 1 (over n1; n = 3*n1 + n2)
            float2 A00,A10,A20, A01,A11,A21, A02,A12,A22;
            dft3<+1>(a0,a3,a6, A00,A10,A20);
            dft3<+1>(a1,a4,a7, A01,A11,A21);
            dft3<+1>(a2,a5,a8, A02,A12,A22);
            A11 = cmul(A11, C91, -S91);
            A12 = cmul(A12, C92, -S92);
            A21 = cmul(A21, C92, -S92);
            A22 = cmul(A22, C94, -S94);
            // per-group: fwd stage2 -> weight -> inv stage1
            float2 P00,P10,P20, P01,P11,P21, P02,P12,P22;
            {
                float2 X0,X3,X6;
                dft3<+1>(A00,A01,A02, X0,X3,X6);
                X0 = wmul(X0, cwp[0*WS]); X3 = wmul(X3, cwp[3*WS]); X6 = wmul(X6, cwp[6*WS]);
                dft3<-1>(X0,X3,X6, P00,P10,P20);
            }
            {
                float2 X1,X4,X7;
                dft3<+1>(A10,A11,A12, X1,X4,X7);
                X1 = wmul(X1, cwp[1*WS]); X4 = wmul(X4, cwp[4*WS]); X7 = wmul(X7, cwp[7*WS]);
                dft3<-1>(X1,X4,X7, P01,P11,P21);
            }
            {
                float2 X2,X5,X8;
                dft3<+1>(A20,A21,A22, X2,X5,X8);
                X2 = wmul(X2, cwp[2*WS]); X5 = wmul(X5, cwp[5*WS]); X8 = wmul(X8, cwp[8*WS]);
                dft3<-1>(X2,X5,X8, P02,P12,P22);
            }
            // inverse twiddles + stage 2, store per group
            P11 = cmul(P11, C91, S91);
            P12 = cmul(P12, C92, S92);
            P21 = cmul(P21, C92, S92);
            P22 = cmul(P22, C94, S94);
            {
                float2 y0,y3,y6;
                dft3<-1>(P00,P01,P02, y0,y3,y6);
                z[base+0*HS]=y0; z[base+3*HS]=y3; z[base+6*HS]=y6;
            }
            {
                float2 y1,y4,y7;
                dft3<-1>(P10,P11,P12, y1,y4,y7);
                z[base+1*HS]=y1; z[base+4*HS]=y4; z[base+7*HS]=y7;
            }
            {
                float2 y2,y5,y8;
                dft3<-1>(P20,P21,P22, y2,y5,y8);
                z[base+2*HS]=y2; z[base+5*HS]=y5; z[base+8*HS]=y8;
            }
        }
    }
    __syncthreads();

    // ---- Phase 4: inverse FFT along w (radix 2x5), registers
    for (int it = tid; it < Hn*KD*CT; it += NTHREADS) {
        int c  = it % CT;
        int hk = it / CT;
        int h = hk / KD, k = hk % KD;
        int zb = (h*Wn*KD + k)*CT + c;
        float2 p0,p1,p2,p3,p4,p5,p6,p7,p8,p9;
        LOADP();
        fft10s<-1>(p0,p1,p2,p3,p4,p5,p6,p7,p8,p9);
        STOREP();
    }
    __syncthreads();

    // ---- Phase 5: irfft5 along d + store, 4 channels per thread (float4 I/O)
    for (int it = tid; it < Hn*Wn*(CT/4); it += NTHREADS) {
        int c4 = it % (CT/4);
        int hw = it / (CT/4);
        int sb = (hw*KD)*CT + c4*4;
        float4 u0a = *(const float4*)&z[sb];          float4 u0b = *(const float4*)&z[sb + 2];
        float4 u1a = *(const float4*)&z[sb + CT];     float4 u1b = *(const float4*)&z[sb + CT + 2];
        float4 u2a = *(const float4*)&z[sb + 2*CT];   float4 u2b = *(const float4*)&z[sb + 2*CT + 2];
        float4 o0,o1,o2,o3,o4;
        IRFFT5C(u0a.x, u1a.x,u1a.y, u2a.x,u2a.y, o0.x,o1.x,o2.x,o3.x,o4.x);
        IRFFT5C(u0a.z, u1a.z,u1a.w, u2a.z,u2a.w, o0.y,o1.y,o2.y,o3.y,o4.y);
        IRFFT5C(u0b.x, u1b.x,u1b.y, u2b.x,u2b.y, o0.z,o1.z,o2.z,o3.z,o4.z);
        IRFFT5C(u0b.z, u1b.z,u1b.w, u2b.z,u2b.w, o0.w,o1.w,o2.w,o3.w,o4.w);
        float* po = out + xbase + (long)hw * (Dn*DIMC) + c4*4;
        *(float4*)(po)          = o0;
        *(float4*)(po + DIMC)   = o1;
        *(float4*)(po + 2*DIMC) = o2;
        *(float4*)(po + 3*DIMC) = o3;
        *(float4*)(po + 4*DIMC) = o4;
    }
}

extern "C" void kernel_launch(void* const* d_in, const int* in_sizes, int n_in,
                              void* d_out, int out_size) {
    const float*  x   = (const float*)d_in[0];    // (B, 450, 1000) f32
    const float2* cw2 = (const float2*)d_in[1];   // (9, 10, 3, 1000, 2) f32
    float* out = (float*)d_out;                   // (B, 450, 1000) f32
    const int B = in_sizes[0] / (NSP * DIMC);
    dim3 grid(B, DIMC / CT);
    gf_kernel<<<grid, NTHREADS>>>(x, cw2, out);
}

// round 11
// speedup vs baseline: 1.5740x; 1.5740x over previous
#include <cuda_runtime.h>

#define Hn 9
#define Wn 10
#define Dn 5
#define KD 3            // Dn/2 + 1
#define DIMC 1000
#define NSP (Hn*Wn*Dn)  // 450
#define CT 20           // channels per block tile (1000/20 = 50 tiles)
#define NTHREADS 256
#define SC (1.0f/450.0f)

// ---- compile-time twiddle literals (FFMA immediates) ----
#define C51  0.30901699437494745f
#define C52 (-0.8090169943749475f)
#define S51  0.9510565162951535f
#define S52  0.5877852522924731f
#define S3   0.8660254037844386f
#define C91  0.766044443118978f
#define S91  0.6427876096865393f
#define C92  0.17364817766693041f
#define S92  0.984807753012208f
#define C94 (-0.9396926207859084f)
#define S94  0.3420201433256687f
#define C101 0.8090169943749475f
#define S101 0.5877852522924731f
#define C102 0.30901699437494745f
#define S102 0.9510565162951535f
// output-stage constants with 1/450 and the rfft doubling folded in
#define TWOSC (2.0f*SC)
#define C51T (2.0f*SC*C51)
#define C52T (2.0f*SC*C52)
#define S51T (2.0f*SC*S51)
#define S52T (2.0f*SC*S52)

__device__ __forceinline__ float2 cadd(float2 a, float2 b){ return make_float2(a.x+b.x, a.y+b.y); }
__device__ __forceinline__ float2 csub(float2 a, float2 b){ return make_float2(a.x-b.x, a.y-b.y); }
__device__ __forceinline__ float2 cmul(float2 a, float c, float s){
    return make_float2(a.x*c - a.y*s, a.y*c + a.x*s);
}
__device__ __forceinline__ float2 wmul(float2 a, float2 g){
    return make_float2(a.x*g.x - a.y*g.y, a.x*g.y + a.y*g.x);
}

template<int SGN>
__device__ __forceinline__ void dft3(float2 a0, float2 a1, float2 a2,
                                     float2& X0, float2& X1, float2& X2){
    float2 t = cadd(a1,a2), d = csub(a1,a2);
    X0 = cadd(a0,t);
    float mr = fmaf(-0.5f, t.x, a0.x);
    float mi = fmaf(-0.5f, t.y, a0.y);
    const float s = (SGN > 0) ? S3 : -S3;
    X1 = make_float2(fmaf( s, d.y, mr), fmaf(-s, d.x, mi));
    X2 = make_float2(fmaf(-s, d.y, mr), fmaf( s, d.x, mi));
}

template<int SGN>
__device__ __forceinline__ void dft5(float2 a0, float2 a1, float2 a2, float2 a3, float2 a4,
                                     float2& X0, float2& X1, float2& X2, float2& X3, float2& X4){
    float2 t1 = cadd(a1,a4), t2 = cadd(a2,a3), t3 = csub(a1,a4), t4 = csub(a2,a3);
    X0 = make_float2(a0.x + t1.x + t2.x, a0.y + t1.y + t2.y);
    float u1r = a0.x + C51*t1.x + C52*t2.x;
    float u1i = a0.y + C51*t1.y + C52*t2.y;
    float v1r = S51*t3.x + S52*t4.x;
    float v1i = S51*t3.y + S52*t4.y;
    float u2r = a0.x + C52*t1.x + C51*t2.x;
    float u2i = a0.y + C52*t1.y + C51*t2.y;
    float v2r = S52*t3.x - S51*t4.x;
    float v2i = S52*t3.y - S51*t4.y;
    if (SGN > 0){
        X1 = make_float2(u1r + v1i, u1i - v1r);
        X4 = make_float2(u1r - v1i, u1i + v1r);
        X2 = make_float2(u2r + v2i, u2i - v2r);
        X3 = make_float2(u2r - v2i, u2i + v2r);
    } else {
        X1 = make_float2(u1r - v1i, u1i + v1r);
        X4 = make_float2(u1r + v1i, u1i - v1r);
        X2 = make_float2(u2r - v2i, u2i + v2r);
        X3 = make_float2(u2r + v2i, u2i - v2r);
    }
}

// 10-pt FFT on ten named scalars, radix 2x5 DIT
template<int SGN>
__device__ __forceinline__ void fft10s(float2&x0, float2&x1, float2&x2, float2&x3, float2&x4,
                                       float2&x5, float2&x6, float2&x7, float2&x8, float2&x9){
    float2 E0,E1,E2,E3,E4, O0,O1,O2,O3,O4;
    dft5<SGN>(x0,x2,x4,x6,x8, E0,E1,E2,E3,E4);
    dft5<SGN>(x1,x3,x5,x7,x9, O0,O1,O2,O3,O4);
    const float sg = (SGN > 0) ? -1.0f : 1.0f;
    float2 T1 = cmul(O1,  C101, sg*S101);
    float2 T2 = cmul(O2,  C102, sg*S102);
    float2 T3 = cmul(O3, -C102, sg*S102);
    float2 T4 = cmul(O4, -C101, sg*S101);
    x0=cadd(E0,O0); x5=csub(E0,O0);
    x1=cadd(E1,T1); x6=csub(E1,T1);
    x2=cadd(E2,T2); x7=csub(E2,T2);
    x3=cadd(E3,T3); x8=csub(E3,T3);
    x4=cadd(E4,T4); x9=csub(E4,T4);
}

#define DECLK(K) float2 k##K##_0,k##K##_1,k##K##_2,k##K##_3,k##K##_4, \
                        k##K##_5,k##K##_6,k##K##_7,k##K##_8,k##K##_9

#define RFFT5W(w) do { \
    float v0 = px[((w)*Dn+0)*DIMC], v1 = px[((w)*Dn+1)*DIMC], \
          v2 = px[((w)*Dn+2)*DIMC], v3 = px[((w)*Dn+3)*DIMC], \
          v4 = px[((w)*Dn+4)*DIMC]; \
    float t1 = v1+v4, t2 = v2+v3, t3 = v1-v4, t4 = v2-v3; \
    k0_##w = make_float2(v0 + t1 + t2, 0.0f); \
    k1_##w = make_float2(v0 + C51*t1 + C52*t2, -(S51*t3 + S52*t4)); \
    k2_##w = make_float2(v0 + C52*t1 + C51*t2, -(S52*t3 - S51*t4)); \
} while(0)

#define FFT10K(SGN, K) fft10s<SGN>(k##K##_0,k##K##_1,k##K##_2,k##K##_3,k##K##_4, \
                                   k##K##_5,k##K##_6,k##K##_7,k##K##_8,k##K##_9)

#define STOREK(K) do { \
    z[zb + (0*KD+(K))*CT] = k##K##_0; z[zb + (1*KD+(K))*CT] = k##K##_1; \
    z[zb + (2*KD+(K))*CT] = k##K##_2; z[zb + (3*KD+(K))*CT] = k##K##_3; \
    z[zb + (4*KD+(K))*CT] = k##K##_4; z[zb + (5*KD+(K))*CT] = k##K##_5; \
    z[zb + (6*KD+(K))*CT] = k##K##_6; z[zb + (7*KD+(K))*CT] = k##K##_7; \
    z[zb + (8*KD+(K))*CT] = k##K##_8; z[zb + (9*KD+(K))*CT] = k##K##_9; \
} while(0)

#define LOADKP(K) do { \
    k##K##_0 = z[zb + (0*KD+(K))*CT]; k##K##_1 = z[zb + (1*KD+(K))*CT]; \
    k##K##_2 = z[zb + (2*KD+(K))*CT]; k##K##_3 = z[zb + (3*KD+(K))*CT]; \
    k##K##_4 = z[zb + (4*KD+(K))*CT]; k##K##_5 = z[zb + (5*KD+(K))*CT]; \
    k##K##_6 = z[zb + (6*KD+(K))*CT]; k##K##_7 = z[zb + (7*KD+(K))*CT]; \
    k##K##_8 = z[zb + (8*KD+(K))*CT]; k##K##_9 = z[zb + (9*KD+(K))*CT]; \
} while(0)

// irfft5 + store for one w, with 1/450 and rfft doubling folded into constants
#define OUTW(w) do { \
    float s0 = SC * k0_##w.x; \
    float r1 = k1_##w.x, i1 = k1_##w.y, r2 = k2_##w.x, i2 = k2_##w.y; \
    float pA = s0 + C51T*r1 + C52T*r2; \
    float qA = S51T*i1 + S52T*i2; \
    float pB = s0 + C52T*r1 + C51T*r2; \
    float qB = S52T*i1 - S51T*i2; \
    po[((w)*Dn+0)*DIMC] = s0 + TWOSC*(r1 + r2); \
    po[((w)*Dn+1)*DIMC] = pA - qA; \
    po[((w)*Dn+2)*DIMC] = pB - qB; \
    po[((w)*Dn+3)*DIMC] = pB + qB; \
    po[((w)*Dn+4)*DIMC] = pA + qA; \
} while(0)

// Shared layout: z[((h*Wn + w)*KD + k)*CT + c] as float2 — 43.2 KB STATIC
// (static smem is what lets ptxas see the true occupancy bound and grant
//  the ~100 registers the pencil dataflow needs instead of clamping to 64)
__global__ void __launch_bounds__(NTHREADS, 2)
gf_kernel(const float* __restrict__ x, const float2* __restrict__ cw2,
          float* __restrict__ out)
{
    __shared__ float2 z[Hn*Wn*KD*CT];

    const int b   = blockIdx.x;
    const int c0  = blockIdx.y * CT;
    const int tid = threadIdx.x;
    const long xbase = (long)b * NSP * DIMC + c0;

    // ---- Phase A: thread owns (h, c) pencil: 50 coalesced global loads,
    //      10x rfft5 (d) + 3x fft10 (w) in named scalars, per-plane shared store.
    for (int it = tid; it < Hn*CT; it += NTHREADS) {
        int c = it % CT, h = it / CT;
        const float* px = x + xbase + (long)h * (Wn*Dn*DIMC) + c;
        int zb = (h*Wn*KD)*CT + c;
        DECLK(0); DECLK(1); DECLK(2);
        RFFT5W(0); RFFT5W(1); RFFT5W(2); RFFT5W(3); RFFT5W(4);
        RFFT5W(5); RFFT5W(6); RFFT5W(7); RFFT5W(8); RFFT5W(9);
        FFT10K(+1, 0); STOREK(0);
        FFT10K(+1, 1); STOREK(1);
        FFT10K(+1, 2); STOREK(2);
    }
    __syncthreads();

    // ---- Phase B: fwd 9-pt (3x3) -> weight -> inv 9-pt, in registers
    {
        const int HS = Wn*KD*CT;
        const int WS = Wn*KD*DIMC;
        for (int it = tid; it < Wn*KD*CT; it += NTHREADS) {
            int c  = it % CT;
            int wk = it / CT;
            int w = wk / KD, k = wk % KD;
            int base = (w*KD + k)*CT + c;
            const float2* cwp = cw2 + (long)((w*KD) + k)*DIMC + c0 + c;
            float2 a0=z[base+0*HS], a1=z[base+1*HS], a2=z[base+2*HS],
                   a3=z[base+3*HS], a4=z[base+4*HS], a5=z[base+5*HS],
                   a6=z[base+6*HS], a7=z[base+7*HS], a8=z[base+8*HS];
            float2 A00,A10,A20, A01,A11,A21, A02,A12,A22;
            dft3<+1>(a0,a3,a6, A00,A10,A20);
            dft3<+1>(a1,a4,a7, A01,A11,A21);
            dft3<+1>(a2,a5,a8, A02,A12,A22);
            A11 = cmul(A11, C91, -S91);
            A12 = cmul(A12, C92, -S92);
            A21 = cmul(A21, C92, -S92);
            A22 = cmul(A22, C94, -S94);
            float2 X0,X3,X6, X1,X4,X7, X2,X5,X8;
            dft3<+1>(A00,A01,A02, X0,X3,X6);
            dft3<+1>(A10,A11,A12, X1,X4,X7);
            dft3<+1>(A20,A21,A22, X2,X5,X8);
            X0 = wmul(X0, cwp[0*WS]); X1 = wmul(X1, cwp[1*WS]); X2 = wmul(X2, cwp[2*WS]);
            X3 = wmul(X3, cwp[3*WS]); X4 = wmul(X4, cwp[4*WS]); X5 = wmul(X5, cwp[5*WS]);
            X6 = wmul(X6, cwp[6*WS]); X7 = wmul(X7, cwp[7*WS]); X8 = wmul(X8, cwp[8*WS]);
            float2 P00,P10,P20, P01,P11,P21, P02,P12,P22;
            dft3<-1>(X0,X3,X6, P00,P10,P20);
            dft3<-1>(X1,X4,X7, P01,P11,P21);
            dft3<-1>(X2,X5,X8, P02,P12,P22);
            P11 = cmul(P11, C91, S91);
            P12 = cmul(P12, C92, S92);
            P21 = cmul(P21, C92, S92);
            P22 = cmul(P22, C94, S94);
            float2 y0,y3,y6, y1,y4,y7, y2,y5,y8;
            dft3<-1>(P00,P01,P02, y0,y3,y6);
            dft3<-1>(P10,P11,P12, y1,y4,y7);
            dft3<-1>(P20,P21,P22, y2,y5,y8);
            z[base+0*HS]=y0; z[base+1*HS]=y1; z[base+2*HS]=y2;
            z[base+3*HS]=y3; z[base+4*HS]=y4; z[base+5*HS]=y5;
            z[base+6*HS]=y6; z[base+7*HS]=y7; z[base+8*HS]=y8;
        }
    }
    __syncthreads();

    // ---- Phase C: thread owns (h, c) pencil: per-plane shared load + ifft10,
    //      then 10x irfft5 (d) and 50 coalesced global stores.
    for (int it = tid; it < Hn*CT; it += NTHREADS) {
        int c = it % CT, h = it / CT;
        int zb = (h*Wn*KD)*CT + c;
        DECLK(0); DECLK(1); DECLK(2);
        LOADKP(0); FFT10K(-1, 0);
        LOADKP(1); FFT10K(-1, 1);
        LOADKP(2); FFT10K(-1, 2);
        float* po = out + xbase + (long)h * (Wn*Dn*DIMC) + c;
        OUTW(0); OUTW(1); OUTW(2); OUTW(3); OUTW(4);
        OUTW(5); OUTW(6); OUTW(7); OUTW(8); OUTW(9);
    }
}

extern "C" void kernel_launch(void* const* d_in, const int* in_sizes, int n_in,
                              void* d_out, int out_size) {
    const float*  x   = (const float*)d_in[0];    // (B, 450, 1000) f32
    const float2* cw2 = (const float2*)d_in[1];   // (9, 10, 3, 1000, 2) f32
    float* out = (float*)d_out;                   // (B, 450, 1000) f32
    const int B = in_sizes[0] / (NSP * DIMC);
    dim3 grid(B, DIMC / CT);
    gf_kernel<<<grid, NTHREADS>>>(x, cw2, out);
}